// round 4
// baseline (speedup 1.0000x reference)
#include <cuda_runtime.h>

#define B_ 512
#define N_ 64
#define L_ 64
#define D_ 100
#define NNODES 50000
#define NLOGITS 49999
#define ROWS (B_*N_)   // 32768

// ---------------- scratch (device globals; no allocation allowed) ----------
__device__ float g_fin[ROWS*D_];        // h
__device__ float g_fi [ROWS*D_];
__device__ float g_fo [ROWS*D_];
__device__ float g_x1 [ROWS*3*D_];      // [av(200) | h(100)]
__device__ float g_gates[ROWS*2*D_];    // [r(100) | u(100)]
__device__ float g_x2 [ROWS*3*D_];      // [av(200) | r*h(100)]
__device__ float g_re [ROWS*D_];
__device__ float g_seqh[B_*L_*D_];
__device__ float g_seq [B_*L_*D_];
__device__ float g_lasth[B_*D_];
__device__ float g_last [B_*D_];
__device__ float g_ma   [B_*D_];
__device__ float g_logp [B_];

// ---------------- fast math: FMA-poly exp (avoid MUFU throughput wall) -----
__device__ __forceinline__ float fexp(float x){
    x = fminf(fmaxf(x, -87.0f), 87.0f);
    float n = rintf(x * 1.4426950408889634f);
    float f = fmaf(n, -0.693359375f, x);
    f = fmaf(n, 2.12194440054690583e-4f, f);
    float p = 1.3888889e-3f;
    p = fmaf(p, f, 8.3333333e-3f);
    p = fmaf(p, f, 4.1666667e-2f);
    p = fmaf(p, f, 1.6666667e-1f);
    p = fmaf(p, f, 0.5f);
    p = fmaf(p, f, 1.0f);
    p = fmaf(p, f, 1.0f);
    int e = (int)n;
    float s = __int_as_float((e + 127) << 23);
    return p * s;
}
__device__ __forceinline__ float fsigmoid(float x){
    return __fdividef(1.0f, 1.0f + fexp(-x));
}
__device__ __forceinline__ float ftanh(float x){
    return __fdividef(2.0f, 1.0f + fexp(-2.0f * x)) - 1.0f;
}

// ---------------- generic register-tiled GEMM: C = act(A[M,K] @ W[K,N] + b)
// BLK 64x64, BK=25 (K must be a multiple of 25: 100 or 300 here)
// MODE 0: none; MODE 1: sigmoid; MODE 2: GRU candidate+update epilogue
template<int MODE>
__global__ void gemm64(const float* __restrict__ A, const float* __restrict__ W,
                       const float* __restrict__ bias, float* __restrict__ C,
                       int M, int K, int N)
{
    __shared__ float sA[64][25];
    __shared__ float sW[25][64];
    int m0 = blockIdx.y * 64;
    int n0 = blockIdx.x * 64;
    int tid = threadIdx.x;
    int tx = tid & 15, ty = tid >> 4;
    float acc[4][4] = {};

    for (int k0 = 0; k0 < K; k0 += 25){
        for (int t = tid; t < 64*25; t += 256){
            int r = t / 25, c = t % 25;
            sA[r][c] = (m0 + r < M) ? A[(m0 + r) * K + k0 + c] : 0.0f;
        }
        for (int t = tid; t < 25*64; t += 256){
            int kk = t >> 6, j = t & 63;
            int n = n0 + j;
            sW[kk][j] = (n < N) ? W[(k0 + kk) * N + n] : 0.0f;
        }
        __syncthreads();
        #pragma unroll
        for (int kk = 0; kk < 25; kk++){
            float a0 = sA[ty*4+0][kk];
            float a1 = sA[ty*4+1][kk];
            float a2 = sA[ty*4+2][kk];
            float a3 = sA[ty*4+3][kk];
            float4 w = *(const float4*)&sW[kk][tx*4];
            acc[0][0] = fmaf(a0, w.x, acc[0][0]); acc[0][1] = fmaf(a0, w.y, acc[0][1]);
            acc[0][2] = fmaf(a0, w.z, acc[0][2]); acc[0][3] = fmaf(a0, w.w, acc[0][3]);
            acc[1][0] = fmaf(a1, w.x, acc[1][0]); acc[1][1] = fmaf(a1, w.y, acc[1][1]);
            acc[1][2] = fmaf(a1, w.z, acc[1][2]); acc[1][3] = fmaf(a1, w.w, acc[1][3]);
            acc[2][0] = fmaf(a2, w.x, acc[2][0]); acc[2][1] = fmaf(a2, w.y, acc[2][1]);
            acc[2][2] = fmaf(a2, w.z, acc[2][2]); acc[2][3] = fmaf(a2, w.w, acc[2][3]);
            acc[3][0] = fmaf(a3, w.x, acc[3][0]); acc[3][1] = fmaf(a3, w.y, acc[3][1]);
            acc[3][2] = fmaf(a3, w.z, acc[3][2]); acc[3][3] = fmaf(a3, w.w, acc[3][3]);
        }
        __syncthreads();
    }

    #pragma unroll
    for (int q = 0; q < 4; q++){
        int row = m0 + ty*4 + q;
        if (row >= M) continue;
        #pragma unroll
        for (int p = 0; p < 4; p++){
            int col = n0 + tx*4 + p;
            if (col >= N) continue;
            float v = acc[q][p];
            if (bias) v += bias[col];
            if (MODE == 1) v = fsigmoid(v);
            if (MODE == 2){
                float c = ftanh(v);
                float u = g_gates[row*200 + 100 + col];
                float h = g_fin[row*100 + col];
                v = u*h + (1.0f - u)*c;
            }
            C[(long long)row * N + col] = v;
        }
    }
}

// ---------------- logits: C[m,n] = dot(A[m,:], E[n,:])  (NT layout) --------
__global__ void gemm_nt_logits(const float* __restrict__ A, const float* __restrict__ E,
                               float* __restrict__ C, int M, long long NC)
{
    __shared__ float sA[64][25];
    __shared__ float sE[64][25];
    int m0 = blockIdx.y * 64;
    long long n0 = (long long)blockIdx.x * 64;
    int tid = threadIdx.x;
    int tx = tid & 15, ty = tid >> 4;
    float acc[4][4] = {};

    for (int k0 = 0; k0 < 100; k0 += 25){
        for (int t = tid; t < 64*25; t += 256){
            int r = t / 25, c = t % 25;
            sA[r][c] = (m0 + r < M) ? A[(m0 + r) * 100 + k0 + c] : 0.0f;
        }
        for (int t = tid; t < 64*25; t += 256){
            int r = t / 25, c = t % 25;
            long long n = n0 + r;
            sE[r][c] = (n < NC) ? E[n * 100 + k0 + c] : 0.0f;
        }
        __syncthreads();
        #pragma unroll
        for (int kk = 0; kk < 25; kk++){
            float a0 = sA[ty*4+0][kk];
            float a1 = sA[ty*4+1][kk];
            float a2 = sA[ty*4+2][kk];
            float a3 = sA[ty*4+3][kk];
            float e0 = sE[tx*4+0][kk];
            float e1 = sE[tx*4+1][kk];
            float e2 = sE[tx*4+2][kk];
            float e3 = sE[tx*4+3][kk];
            acc[0][0] = fmaf(a0, e0, acc[0][0]); acc[0][1] = fmaf(a0, e1, acc[0][1]);
            acc[0][2] = fmaf(a0, e2, acc[0][2]); acc[0][3] = fmaf(a0, e3, acc[0][3]);
            acc[1][0] = fmaf(a1, e0, acc[1][0]); acc[1][1] = fmaf(a1, e1, acc[1][1]);
            acc[1][2] = fmaf(a1, e2, acc[1][2]); acc[1][3] = fmaf(a1, e3, acc[1][3]);
            acc[2][0] = fmaf(a2, e0, acc[2][0]); acc[2][1] = fmaf(a2, e1, acc[2][1]);
            acc[2][2] = fmaf(a2, e2, acc[2][2]); acc[2][3] = fmaf(a2, e3, acc[2][3]);
            acc[3][0] = fmaf(a3, e0, acc[3][0]); acc[3][1] = fmaf(a3, e1, acc[3][1]);
            acc[3][2] = fmaf(a3, e2, acc[3][2]); acc[3][3] = fmaf(a3, e3, acc[3][3]);
        }
        __syncthreads();
    }
    #pragma unroll
    for (int q = 0; q < 4; q++){
        int row = m0 + ty*4 + q;
        if (row >= M) continue;
        #pragma unroll
        for (int p = 0; p < 4; p++){
            long long col = n0 + tx*4 + p;
            if (col >= NC) continue;
            C[(long long)row * NC + col] = acc[q][p];
        }
    }
}

// ---------------- small kernels --------------------------------------------
__global__ void k_gather(const float* __restrict__ emb, const int* __restrict__ item){
    int t = blockIdx.x * 256 + threadIdx.x;
    if (t >= ROWS * D_) return;
    int idx = t / D_, d = t % D_;
    float v = emb[(long long)item[idx] * D_ + d];
    g_fin[t] = v;
    g_x1[idx * 300 + 200 + d] = v;   // h-part of concat for gates GEMM
}

// av = [adj_in @ fi | adj_out @ fo] -> x1[:, 0:200]
__global__ void k_av(const float* __restrict__ adj_in, const float* __restrict__ adj_out){
    int b = blockIdx.x;
    __shared__ float sAi[64*64];
    __shared__ float sAo[64*64];
    for (int t = threadIdx.x; t < 4096; t += 256){
        sAi[t] = adj_in [b*4096 + t];
        sAo[t] = adj_out[b*4096 + t];
    }
    __syncthreads();
    const float* fi = g_fi + b*64*100;
    const float* fo = g_fo + b*64*100;
    float* x1 = g_x1 + b*64*300;
    for (int t = threadIdx.x; t < 100*16; t += 256){
        int e = t % 100, iq = t / 100;
        int i0 = iq * 4;
        float aI[4] = {0,0,0,0}, aO[4] = {0,0,0,0};
        for (int j = 0; j < 64; j++){
            float vI = __ldg(&fi[j*100 + e]);
            float vO = __ldg(&fo[j*100 + e]);
            #pragma unroll
            for (int q = 0; q < 4; q++){
                aI[q] = fmaf(sAi[(i0+q)*64 + j], vI, aI[q]);
                aO[q] = fmaf(sAo[(i0+q)*64 + j], vO, aO[q]);
            }
        }
        #pragma unroll
        for (int q = 0; q < 4; q++){
            x1[(i0+q)*300 + e]       = aI[q];
            x1[(i0+q)*300 + 100 + e] = aO[q];
        }
    }
}

// x2 = [av | r*h]
__global__ void k_x2(){
    int t = blockIdx.x * 256 + threadIdx.x;
    if (t >= ROWS * 300) return;
    int row = t / 300, c = t % 300;
    float v;
    if (c < 200) v = g_x1[t];
    else {
        int d = c - 200;
        v = g_gates[row*200 + d] * g_fin[row*100 + d];
    }
    g_x2[t] = v;
}

// per-batch: rm, last_id, gather seq_h and last_h
__global__ void k_nasr(const int* __restrict__ alias, const float* __restrict__ mask){
    int b = blockIdx.x;
    __shared__ int s_alias[64];
    __shared__ int s_last;
    if (threadIdx.x < 64) s_alias[threadIdx.x] = alias[b*64 + threadIdx.x];
    __syncthreads();
    if (threadIdx.x == 0){
        float s = 0.0f;
        for (int l = 0; l < 64; l++) s += mask[b*64 + l];
        int rm = (int)(s + 0.5f);
        if (rm < 1) rm = 1;
        s_last = s_alias[rm - 1];
    }
    __syncthreads();
    for (int t = threadIdx.x; t < 64*100; t += 256){
        int l = t / 100, d = t % 100;
        g_seqh[(b*64 + l)*100 + d] = g_re[(b*64 + s_alias[l])*100 + d];
    }
    for (int d = threadIdx.x; d < 100; d += 256)
        g_lasth[b*100 + d] = g_re[(b*64 + s_last)*100 + d];
}

// attention: coef + weighted sum -> ma
__global__ void k_attn(const float* __restrict__ mask, const float* __restrict__ nasr_v,
                       const float* __restrict__ nasr_b){
    int b = blockIdx.x;
    int tid = threadIdx.x;               // 128 threads
    __shared__ float s_last[100], s_v[100], s_nb[100], s_coef[64];
    if (tid < 100){
        s_last[tid] = g_last[b*100 + tid];
        s_v[tid]    = nasr_v[tid];
        s_nb[tid]   = nasr_b[tid];
    }
    __syncthreads();
    int w = tid >> 5, lane = tid & 31;
    for (int l = w; l < 64; l += 4){
        float part = 0.0f;
        for (int d = lane; d < 100; d += 32){
            float x = s_last[d] + g_seq[(b*64 + l)*100 + d] + s_nb[d];
            part = fmaf(fsigmoid(x), s_v[d], part);
        }
        #pragma unroll
        for (int o = 16; o > 0; o >>= 1) part += __shfl_down_sync(0xffffffffu, part, o);
        if (lane == 0) s_coef[l] = part * mask[b*64 + l];
    }
    __syncthreads();
    for (int d = tid; d < 100; d += 128){
        float acc = 0.0f;
        for (int l = 0; l < 64; l++)
            acc = fmaf(s_coef[l], g_seqh[(b*64 + l)*100 + d], acc);
        g_ma[b*100 + d] = acc;
    }
}

// per-row online max/sumexp over logits, then logp[label]
__global__ void k_rowstat(const float* __restrict__ logits, const int* __restrict__ tar){
    int b = blockIdx.x;
    const float* row = logits + (long long)b * NLOGITS;
    int tid = threadIdx.x;
    float m = -1e30f, s = 0.0f;
    for (int j = tid; j < NLOGITS; j += 256){
        float x = row[j];
        if (x > m){ s = fmaf(s, fexp(m - x), 1.0f); m = x; }
        else       s += fexp(x - m);
    }
    __shared__ float sm[256], ss[256];
    sm[tid] = m; ss[tid] = s;
    __syncthreads();
    for (int o = 128; o > 0; o >>= 1){
        if (tid < o){
            float m2 = sm[tid+o], s2 = ss[tid+o];
            float M = fmaxf(sm[tid], m2);
            ss[tid] = ss[tid]*fexp(sm[tid]-M) + s2*fexp(m2-M);
            sm[tid] = M;
        }
        __syncthreads();
    }
    if (tid == 0){
        int lab = tar[b] - 1;
        g_logp[b] = row[lab] - sm[0] - logf(ss[0]);
    }
}

__global__ void k_loss(float* __restrict__ out, int off){
    __shared__ float sh[512];
    int tid = threadIdx.x;
    sh[tid] = g_logp[tid];
    __syncthreads();
    for (int o = 256; o > 0; o >>= 1){
        if (tid < o) sh[tid] += sh[tid+o];
        __syncthreads();
    }
    if (tid == 0){
        float loss = -sh[0] / (float)B_;
        for (int i = 0; i < off; i++) out[i] = loss;
    }
}

// ---------------- host ------------------------------------------------------
static float* symf(const void* s){ void* p = nullptr; cudaGetSymbolAddress(&p, s); return (float*)p; }

extern "C" void kernel_launch(void* const* d_in, const int* in_sizes, int n_in,
                              void* d_out, int out_size)
{
    const float* adj_in   = (const float*)d_in[0];
    const float* adj_out  = (const float*)d_in[1];
    const int*   item     = (const int*)  d_in[2];
    const int*   alias    = (const int*)  d_in[3];
    const float* mask     = (const float*)d_in[4];
    const int*   tar      = (const int*)  d_in[5];
    const float* emb      = (const float*)d_in[6];
    const float* W_in     = (const float*)d_in[7];
    const float* b_in     = (const float*)d_in[8];
    const float* W_out    = (const float*)d_in[9];
    const float* b_out    = (const float*)d_in[10];
    const float* gate_k   = (const float*)d_in[11];
    const float* gate_b   = (const float*)d_in[12];
    const float* cand_k   = (const float*)d_in[13];
    const float* cand_b   = (const float*)d_in[14];
    const float* nasr_w1  = (const float*)d_in[15];
    const float* nasr_w2  = (const float*)d_in[16];
    const float* nasr_v   = (const float*)d_in[17];
    const float* nasr_b   = (const float*)d_in[18];

    float* out = (float*)d_out;
    long long nlog = (long long)B_ * NLOGITS;
    int off = out_size - (int)nlog;
    if (off < 0) off = 0;
    float* out_logits = out + off;

    float* p_fin   = symf(g_fin);
    float* p_fi    = symf(g_fi);
    float* p_fo    = symf(g_fo);
    float* p_x1    = symf(g_x1);
    float* p_gates = symf(g_gates);
    float* p_x2    = symf(g_x2);
    float* p_re    = symf(g_re);
    float* p_seqh  = symf(g_seqh);
    float* p_seq   = symf(g_seq);
    float* p_lasth = symf(g_lasth);
    float* p_last  = symf(g_last);
    float* p_ma    = symf(g_ma);

    // 1. gather embeddings (also fills h-part of x1)
    k_gather<<<(ROWS*D_ + 255)/256, 256>>>(emb, item);
    // 2. fi = fin@W_in + b_in ; fo = fin@W_out + b_out
    gemm64<0><<<dim3(2, ROWS/64), 256>>>(p_fin, W_in,  b_in,  p_fi, ROWS, 100, 100);
    gemm64<0><<<dim3(2, ROWS/64), 256>>>(p_fin, W_out, b_out, p_fo, ROWS, 100, 100);
    // 3. av = [adj_in@fi | adj_out@fo] -> x1[:,0:200]
    k_av<<<B_, 256>>>(adj_in, adj_out);
    // 4. gates = sigmoid(x1 @ gate_kernel + gate_bias)
    gemm64<1><<<dim3(4, ROWS/64), 256>>>(p_x1, gate_k, gate_b, p_gates, ROWS, 300, 200);
    // 5. x2 = [av | r*h]
    k_x2<<<(ROWS*300 + 255)/256, 256>>>();
    // 6. c = tanh(x2 @ cand_kernel + cand_bias); re = u*h + (1-u)*c
    gemm64<2><<<dim3(2, ROWS/64), 256>>>(p_x2, cand_k, cand_b, p_re, ROWS, 300, 100);
    // 7. nasr gathers
    k_nasr<<<B_, 256>>>(alias, mask);
    // 8. seq = seqh @ nasr_w2 ; last = lasth @ nasr_w1
    gemm64<0><<<dim3(2, ROWS/64), 256>>>(p_seqh, nasr_w2, nullptr, p_seq, ROWS, 100, 100);
    gemm64<0><<<dim3(2, B_/64), 256>>>(p_lasth, nasr_w1, nullptr, p_last, B_, 100, 100);
    // 9. attention -> ma
    k_attn<<<B_, 128>>>(mask, nasr_v, nasr_b);
    // 10. logits = ma @ emb[1:].T
    gemm_nt_logits<<<dim3((NLOGITS + 63)/64, B_/64), 256>>>(p_ma, emb + D_, out_logits, B_, (long long)NLOGITS);
    // 11. per-row log-softmax stats + loss
    k_rowstat<<<B_, 256>>>(out_logits, tar);
    k_loss<<<1, 512>>>(out, off);
}

// round 5
// speedup vs baseline: 1.0033x; 1.0033x over previous
#include <cuda_runtime.h>

#define B_ 512
#define N_ 64
#define L_ 64
#define D_ 100
#define NNODES 50000
#define NLOGITS 49999
#define ROWS (B_*N_)   // 32768

// ---------------- scratch (device globals; no allocation allowed) ----------
__device__ float g_fin[ROWS*D_];        // h
__device__ float g_fi [ROWS*D_];
__device__ float g_fo [ROWS*D_];
__device__ float g_x1 [ROWS*3*D_];      // [av(200) | h(100)]
__device__ float g_gates[ROWS*2*D_];    // [r(100) | u(100)]
__device__ float g_x2 [ROWS*3*D_];      // [av(200) | r*h(100)]
__device__ float g_re [ROWS*D_];
__device__ float g_seqh[B_*L_*D_];
__device__ float g_seq [B_*L_*D_];
__device__ float g_lasth[B_*D_];
__device__ float g_last [B_*D_];
__device__ float g_ma   [B_*D_];
__device__ float g_logp [B_];

// ---------------- fast math: FMA-poly exp (avoid MUFU throughput wall) -----
__device__ __forceinline__ float fexp(float x){
    x = fminf(fmaxf(x, -87.0f), 87.0f);
    float n = rintf(x * 1.4426950408889634f);
    float f = fmaf(n, -0.693359375f, x);
    f = fmaf(n, 2.12194440054690583e-4f, f);
    float p = 1.3888889e-3f;
    p = fmaf(p, f, 8.3333333e-3f);
    p = fmaf(p, f, 4.1666667e-2f);
    p = fmaf(p, f, 1.6666667e-1f);
    p = fmaf(p, f, 0.5f);
    p = fmaf(p, f, 1.0f);
    p = fmaf(p, f, 1.0f);
    int e = (int)n;
    float s = __int_as_float((e + 127) << 23);
    return p * s;
}
__device__ __forceinline__ float fsigmoid(float x){
    return __fdividef(1.0f, 1.0f + fexp(-x));
}
__device__ __forceinline__ float ftanh(float x){
    return __fdividef(2.0f, 1.0f + fexp(-2.0f * x)) - 1.0f;
}

// ---------------- generic register-tiled GEMM: C = act(A[M,K] @ W[K,N] + b)
// BLK 64x64, BK=25 (K must be a multiple of 25: 100 or 300 here)
// MODE 0: none; MODE 1: sigmoid; MODE 2: GRU candidate+update epilogue
template<int MODE>
__global__ void gemm64(const float* __restrict__ A, const float* __restrict__ W,
                       const float* __restrict__ bias, float* __restrict__ C,
                       int M, int K, int N)
{
    __shared__ float sA[64][25];
    __shared__ float sW[25][64];
    int m0 = blockIdx.y * 64;
    int n0 = blockIdx.x * 64;
    int tid = threadIdx.x;
    int tx = tid & 15, ty = tid >> 4;
    float acc[4][4] = {};

    for (int k0 = 0; k0 < K; k0 += 25){
        for (int t = tid; t < 64*25; t += 256){
            int r = t / 25, c = t % 25;
            sA[r][c] = (m0 + r < M) ? A[(m0 + r) * K + k0 + c] : 0.0f;
        }
        for (int t = tid; t < 25*64; t += 256){
            int kk = t >> 6, j = t & 63;
            int n = n0 + j;
            sW[kk][j] = (n < N) ? W[(k0 + kk) * N + n] : 0.0f;
        }
        __syncthreads();
        #pragma unroll
        for (int kk = 0; kk < 25; kk++){
            float a0 = sA[ty*4+0][kk];
            float a1 = sA[ty*4+1][kk];
            float a2 = sA[ty*4+2][kk];
            float a3 = sA[ty*4+3][kk];
            float4 w = *(const float4*)&sW[kk][tx*4];
            acc[0][0] = fmaf(a0, w.x, acc[0][0]); acc[0][1] = fmaf(a0, w.y, acc[0][1]);
            acc[0][2] = fmaf(a0, w.z, acc[0][2]); acc[0][3] = fmaf(a0, w.w, acc[0][3]);
            acc[1][0] = fmaf(a1, w.x, acc[1][0]); acc[1][1] = fmaf(a1, w.y, acc[1][1]);
            acc[1][2] = fmaf(a1, w.z, acc[1][2]); acc[1][3] = fmaf(a1, w.w, acc[1][3]);
            acc[2][0] = fmaf(a2, w.x, acc[2][0]); acc[2][1] = fmaf(a2, w.y, acc[2][1]);
            acc[2][2] = fmaf(a2, w.z, acc[2][2]); acc[2][3] = fmaf(a2, w.w, acc[2][3]);
            acc[3][0] = fmaf(a3, w.x, acc[3][0]); acc[3][1] = fmaf(a3, w.y, acc[3][1]);
            acc[3][2] = fmaf(a3, w.z, acc[3][2]); acc[3][3] = fmaf(a3, w.w, acc[3][3]);
        }
        __syncthreads();
    }

    #pragma unroll
    for (int q = 0; q < 4; q++){
        int row = m0 + ty*4 + q;
        if (row >= M) continue;
        #pragma unroll
        for (int p = 0; p < 4; p++){
            int col = n0 + tx*4 + p;
            if (col >= N) continue;
            float v = acc[q][p];
            if (bias) v += bias[col];
            if (MODE == 1) v = fsigmoid(v);
            if (MODE == 2){
                float c = ftanh(v);
                float u = g_gates[row*200 + 100 + col];
                float h = g_fin[row*100 + col];
                v = u*h + (1.0f - u)*c;
            }
            C[(long long)row * N + col] = v;
        }
    }
}

// ---------------- logits: C[m,n] = dot(A[m,:], E[n,:])  (NT layout) --------
__global__ void gemm_nt_logits(const float* __restrict__ A, const float* __restrict__ E,
                               float* __restrict__ C, int M, long long NC)
{
    __shared__ float sA[64][25];
    __shared__ float sE[64][25];
    int m0 = blockIdx.y * 64;
    long long n0 = (long long)blockIdx.x * 64;
    int tid = threadIdx.x;
    int tx = tid & 15, ty = tid >> 4;
    float acc[4][4] = {};

    for (int k0 = 0; k0 < 100; k0 += 25){
        for (int t = tid; t < 64*25; t += 256){
            int r = t / 25, c = t % 25;
            sA[r][c] = (m0 + r < M) ? A[(m0 + r) * 100 + k0 + c] : 0.0f;
        }
        for (int t = tid; t < 64*25; t += 256){
            int r = t / 25, c = t % 25;
            long long n = n0 + r;
            sE[r][c] = (n < NC) ? E[n * 100 + k0 + c] : 0.0f;
        }
        __syncthreads();
        #pragma unroll
        for (int kk = 0; kk < 25; kk++){
            float a0 = sA[ty*4+0][kk];
            float a1 = sA[ty*4+1][kk];
            float a2 = sA[ty*4+2][kk];
            float a3 = sA[ty*4+3][kk];
            float e0 = sE[tx*4+0][kk];
            float e1 = sE[tx*4+1][kk];
            float e2 = sE[tx*4+2][kk];
            float e3 = sE[tx*4+3][kk];
            acc[0][0] = fmaf(a0, e0, acc[0][0]); acc[0][1] = fmaf(a0, e1, acc[0][1]);
            acc[0][2] = fmaf(a0, e2, acc[0][2]); acc[0][3] = fmaf(a0, e3, acc[0][3]);
            acc[1][0] = fmaf(a1, e0, acc[1][0]); acc[1][1] = fmaf(a1, e1, acc[1][1]);
            acc[1][2] = fmaf(a1, e2, acc[1][2]); acc[1][3] = fmaf(a1, e3, acc[1][3]);
            acc[2][0] = fmaf(a2, e0, acc[2][0]); acc[2][1] = fmaf(a2, e1, acc[2][1]);
            acc[2][2] = fmaf(a2, e2, acc[2][2]); acc[2][3] = fmaf(a2, e3, acc[2][3]);
            acc[3][0] = fmaf(a3, e0, acc[3][0]); acc[3][1] = fmaf(a3, e1, acc[3][1]);
            acc[3][2] = fmaf(a3, e2, acc[3][2]); acc[3][3] = fmaf(a3, e3, acc[3][3]);
        }
        __syncthreads();
    }
    #pragma unroll
    for (int q = 0; q < 4; q++){
        int row = m0 + ty*4 + q;
        if (row >= M) continue;
        #pragma unroll
        for (int p = 0; p < 4; p++){
            long long col = n0 + tx*4 + p;
            if (col >= NC) continue;
            C[(long long)row * NC + col] = acc[q][p];
        }
    }
}

// ---------------- small kernels --------------------------------------------
__global__ void k_gather(const float* __restrict__ emb, const int* __restrict__ item){
    int t = blockIdx.x * 256 + threadIdx.x;
    if (t >= ROWS * D_) return;
    int idx = t / D_, d = t % D_;
    float v = emb[(long long)item[idx] * D_ + d];
    g_fin[t] = v;
    g_x1[idx * 300 + 200 + d] = v;   // h-part of concat for gates GEMM
}

// av = [adj_in @ fi | adj_out @ fo] -> x1[:, 0:200]
__global__ void k_av(const float* __restrict__ adj_in, const float* __restrict__ adj_out){
    int b = blockIdx.x;
    __shared__ float sAi[64*64];
    __shared__ float sAo[64*64];
    for (int t = threadIdx.x; t < 4096; t += 256){
        sAi[t] = adj_in [b*4096 + t];
        sAo[t] = adj_out[b*4096 + t];
    }
    __syncthreads();
    const float* fi = g_fi + b*64*100;
    const float* fo = g_fo + b*64*100;
    float* x1 = g_x1 + b*64*300;
    for (int t = threadIdx.x; t < 100*16; t += 256){
        int e = t % 100, iq = t / 100;
        int i0 = iq * 4;
        float aI[4] = {0,0,0,0}, aO[4] = {0,0,0,0};
        for (int j = 0; j < 64; j++){
            float vI = __ldg(&fi[j*100 + e]);
            float vO = __ldg(&fo[j*100 + e]);
            #pragma unroll
            for (int q = 0; q < 4; q++){
                aI[q] = fmaf(sAi[(i0+q)*64 + j], vI, aI[q]);
                aO[q] = fmaf(sAo[(i0+q)*64 + j], vO, aO[q]);
            }
        }
        #pragma unroll
        for (int q = 0; q < 4; q++){
            x1[(i0+q)*300 + e]       = aI[q];
            x1[(i0+q)*300 + 100 + e] = aO[q];
        }
    }
}

// x2 = [av | r*h]
__global__ void k_x2(){
    int t = blockIdx.x * 256 + threadIdx.x;
    if (t >= ROWS * 300) return;
    int row = t / 300, c = t % 300;
    float v;
    if (c < 200) v = g_x1[t];
    else {
        int d = c - 200;
        v = g_gates[row*200 + d] * g_fin[row*100 + d];
    }
    g_x2[t] = v;
}

// per-batch: rm, last_id, gather seq_h and last_h
__global__ void k_nasr(const int* __restrict__ alias, const float* __restrict__ mask){
    int b = blockIdx.x;
    __shared__ int s_alias[64];
    __shared__ int s_last;
    if (threadIdx.x < 64) s_alias[threadIdx.x] = alias[b*64 + threadIdx.x];
    __syncthreads();
    if (threadIdx.x == 0){
        float s = 0.0f;
        for (int l = 0; l < 64; l++) s += mask[b*64 + l];
        int rm = (int)(s + 0.5f);
        if (rm < 1) rm = 1;
        s_last = s_alias[rm - 1];
    }
    __syncthreads();
    for (int t = threadIdx.x; t < 64*100; t += 256){
        int l = t / 100, d = t % 100;
        g_seqh[(b*64 + l)*100 + d] = g_re[(b*64 + s_alias[l])*100 + d];
    }
    for (int d = threadIdx.x; d < 100; d += 256)
        g_lasth[b*100 + d] = g_re[(b*64 + s_last)*100 + d];
}

// attention: coef + weighted sum -> ma
__global__ void k_attn(const float* __restrict__ mask, const float* __restrict__ nasr_v,
                       const float* __restrict__ nasr_b){
    int b = blockIdx.x;
    int tid = threadIdx.x;               // 128 threads
    __shared__ float s_last[100], s_v[100], s_nb[100], s_coef[64];
    if (tid < 100){
        s_last[tid] = g_last[b*100 + tid];
        s_v[tid]    = nasr_v[tid];
        s_nb[tid]   = nasr_b[tid];
    }
    __syncthreads();
    int w = tid >> 5, lane = tid & 31;
    for (int l = w; l < 64; l += 4){
        float part = 0.0f;
        for (int d = lane; d < 100; d += 32){
            float x = s_last[d] + g_seq[(b*64 + l)*100 + d] + s_nb[d];
            part = fmaf(fsigmoid(x), s_v[d], part);
        }
        #pragma unroll
        for (int o = 16; o > 0; o >>= 1) part += __shfl_down_sync(0xffffffffu, part, o);
        if (lane == 0) s_coef[l] = part * mask[b*64 + l];
    }
    __syncthreads();
    for (int d = tid; d < 100; d += 128){
        float acc = 0.0f;
        for (int l = 0; l < 64; l++)
            acc = fmaf(s_coef[l], g_seqh[(b*64 + l)*100 + d], acc);
        g_ma[b*100 + d] = acc;
    }
}

// per-row online max/sumexp over logits, then logp[label]
__global__ void k_rowstat(const float* __restrict__ logits, const int* __restrict__ tar){
    int b = blockIdx.x;
    const float* row = logits + (long long)b * NLOGITS;
    int tid = threadIdx.x;
    float m = -1e30f, s = 0.0f;
    for (int j = tid; j < NLOGITS; j += 256){
        float x = row[j];
        if (x > m){ s = fmaf(s, fexp(m - x), 1.0f); m = x; }
        else       s += fexp(x - m);
    }
    __shared__ float sm[256], ss[256];
    sm[tid] = m; ss[tid] = s;
    __syncthreads();
    for (int o = 128; o > 0; o >>= 1){
        if (tid < o){
            float m2 = sm[tid+o], s2 = ss[tid+o];
            float M = fmaxf(sm[tid], m2);
            ss[tid] = ss[tid]*fexp(sm[tid]-M) + s2*fexp(m2-M);
            sm[tid] = M;
        }
        __syncthreads();
    }
    if (tid == 0){
        int lab = tar[b] - 1;
        g_logp[b] = row[lab] - sm[0] - logf(ss[0]);
    }
}

__global__ void k_loss(float* __restrict__ out, int off){
    __shared__ float sh[512];
    int tid = threadIdx.x;
    sh[tid] = g_logp[tid];
    __syncthreads();
    for (int o = 256; o > 0; o >>= 1){
        if (tid < o) sh[tid] += sh[tid+o];
        __syncthreads();
    }
    if (tid == 0){
        float loss = -sh[0] / (float)B_;
        for (int i = 0; i < off; i++) out[i] = loss;
    }
}

// ---------------- host ------------------------------------------------------
static float* symf(const void* s){ void* p = nullptr; cudaGetSymbolAddress(&p, s); return (float*)p; }

extern "C" void kernel_launch(void* const* d_in, const int* in_sizes, int n_in,
                              void* d_out, int out_size)
{
    const float* adj_in   = (const float*)d_in[0];
    const float* adj_out  = (const float*)d_in[1];
    const int*   item     = (const int*)  d_in[2];
    const int*   alias    = (const int*)  d_in[3];
    const float* mask     = (const float*)d_in[4];
    const int*   tar      = (const int*)  d_in[5];
    const float* emb      = (const float*)d_in[6];
    const float* W_in     = (const float*)d_in[7];
    const float* b_in     = (const float*)d_in[8];
    const float* W_out    = (const float*)d_in[9];
    const float* b_out    = (const float*)d_in[10];
    const float* gate_k   = (const float*)d_in[11];
    const float* gate_b   = (const float*)d_in[12];
    const float* cand_k   = (const float*)d_in[13];
    const float* cand_b   = (const float*)d_in[14];
    const float* nasr_w1  = (const float*)d_in[15];
    const float* nasr_w2  = (const float*)d_in[16];
    const float* nasr_v   = (const float*)d_in[17];
    const float* nasr_b   = (const float*)d_in[18];

    float* out = (float*)d_out;
    long long nlog = (long long)B_ * NLOGITS;
    int off = out_size - (int)nlog;
    if (off < 0) off = 0;
    float* out_logits = out + off;

    float* p_fin   = symf(g_fin);
    float* p_fi    = symf(g_fi);
    float* p_fo    = symf(g_fo);
    float* p_x1    = symf(g_x1);
    float* p_gates = symf(g_gates);
    float* p_x2    = symf(g_x2);
    float* p_re    = symf(g_re);
    float* p_seqh  = symf(g_seqh);
    float* p_seq   = symf(g_seq);
    float* p_lasth = symf(g_lasth);
    float* p_last  = symf(g_last);
    float* p_ma    = symf(g_ma);

    // 1. gather embeddings (also fills h-part of x1)
    k_gather<<<(ROWS*D_ + 255)/256, 256>>>(emb, item);
    // 2. fi = fin@W_in + b_in ; fo = fin@W_out + b_out
    gemm64<0><<<dim3(2, ROWS/64), 256>>>(p_fin, W_in,  b_in,  p_fi, ROWS, 100, 100);
    gemm64<0><<<dim3(2, ROWS/64), 256>>>(p_fin, W_out, b_out, p_fo, ROWS, 100, 100);
    // 3. av = [adj_in@fi | adj_out@fo] -> x1[:,0:200]
    k_av<<<B_, 256>>>(adj_in, adj_out);
    // 4. gates = sigmoid(x1 @ gate_kernel + gate_bias)
    gemm64<1><<<dim3(4, ROWS/64), 256>>>(p_x1, gate_k, gate_b, p_gates, ROWS, 300, 200);
    // 5. x2 = [av | r*h]
    k_x2<<<(ROWS*300 + 255)/256, 256>>>();
    // 6. c = tanh(x2 @ cand_kernel + cand_bias); re = u*h + (1-u)*c
    gemm64<2><<<dim3(2, ROWS/64), 256>>>(p_x2, cand_k, cand_b, p_re, ROWS, 300, 100);
    // 7. nasr gathers
    k_nasr<<<B_, 256>>>(alias, mask);
    // 8. seq = seqh @ nasr_w2 ; last = lasth @ nasr_w1
    gemm64<0><<<dim3(2, ROWS/64), 256>>>(p_seqh, nasr_w2, nullptr, p_seq, ROWS, 100, 100);
    gemm64<0><<<dim3(2, B_/64), 256>>>(p_lasth, nasr_w1, nullptr, p_last, B_, 100, 100);
    // 9. attention -> ma
    k_attn<<<B_, 128>>>(mask, nasr_v, nasr_b);
    // 10. logits = ma @ emb[1:].T
    gemm_nt_logits<<<dim3((NLOGITS + 63)/64, B_/64), 256>>>(p_ma, emb + D_, out_logits, B_, (long long)NLOGITS);
    // 11. per-row log-softmax stats + loss
    k_rowstat<<<B_, 256>>>(out_logits, tar);
    k_loss<<<1, 512>>>(out, off);
}